// round 2
// baseline (speedup 1.0000x reference)
#include <cuda_runtime.h>
#include <cstdint>

#define N_NODES 50000
#define FIN     32
#define FOUT    64
#define KPTS    125
#define KSPL    (KPTS * FIN)      /* 4000 : spline K-dim        */
#define KDIM    (126 * FIN)       /* 4032 : incl. root chunk    */

/* 800 MB scratch for the scattered (node, kernel-point, f_in) tensor */
__device__ float g_T[(size_t)N_NODES * KSPL];
__device__ float g_deg[N_NODES];

/* ------------------------------------------------------------------ */
__global__ void zero_f4(float4* __restrict__ p, long n4) {
    long i = (long)blockIdx.x * blockDim.x + threadIdx.x;
    if (i < n4) p[i] = make_float4(0.f, 0.f, 0.f, 0.f);
}

/* ------------------------------------------------------------------ */
/* Scatter: 8 lanes per edge, each lane owns 4 input features.        */
__global__ void __launch_bounds__(256)
scatter_kernel(const float* __restrict__ x,
               const int* __restrict__ ei,        /* int32! (JAX x64 off) */
               const float* __restrict__ pseudo,
               long E)
{
    long t    = (long)blockIdx.x * blockDim.x + threadIdx.x;
    int  lane = (int)(t & 7);          /* feature quad            */
    long e    = t >> 3;                /* edge id                  */
    if (e >= E) return;

    int dst = ei[e];
    int src = ei[E + e];

    float p0 = pseudo[e * 3 + 0] * 4.0f;   /* kernel_size - is_open = 4 */
    float p1 = pseudo[e * 3 + 1] * 4.0f;
    float p2 = pseudo[e * 3 + 2] * 4.0f;
    float f0 = floorf(p0), f1 = floorf(p1), f2 = floorf(p2);
    float r0 = p0 - f0,    r1 = p1 - f1,    r2 = p2 - f2;
    int   i0 = (int)f0,    i1 = (int)f1,    i2 = (int)f2;

    const float4 xv = *(const float4*)(x + (size_t)src * FIN + lane * 4);

    if (lane == 0) atomicAdd(&g_deg[dst], 1.0f);

    float* Tbase = g_T + (size_t)dst * KSPL + lane * 4;

#pragma unroll
    for (int s = 0; s < 8; ++s) {
        int   b0 = s & 1, b1 = (s >> 1) & 1, b2 = (s >> 2) & 1;
        float basis = (b0 ? r0 : 1.0f - r0)
                    * (b1 ? r1 : 1.0f - r1)
                    * (b2 ? r2 : 1.0f - r2);
        int c0 = i0 + b0; if (c0 >= 5) c0 -= 5;   /* reference's % kernel_size */
        int c1 = i1 + b1; if (c1 >= 5) c1 -= 5;
        int c2 = i2 + b2; if (c2 >= 5) c2 -= 5;
        int   wi = c0 + 5 * c1 + 25 * c2;
        float* ptr = Tbase + (size_t)wi * FIN;
        asm volatile("red.global.add.v4.f32 [%0], {%1,%2,%3,%4};"
                     :: "l"(ptr),
                        "f"(basis * xv.x), "f"(basis * xv.y),
                        "f"(basis * xv.z), "f"(basis * xv.w)
                     : "memory");
    }
}

/* ------------------------------------------------------------------ */
/* tf32 tensor-core GEMM:  out[N,64] = A[N,4032] @ W[4032,64]         */
/* A rows: [ T[n, 0:4000] | x[n,:]*max(deg,1) ]                        */
/* epilogue: acc / max(deg,1) + bias                                   */

#define BM 64
#define BK 32
#define AS_S 36     /* padded smem strides (conflict-free, 16B aligned) */
#define BS_S 68

__device__ __forceinline__ float to_tf32(float v) {
    unsigned u;
    asm("cvt.rna.tf32.f32 %0, %1;" : "=r"(u) : "f"(v));
    return __uint_as_float(u);
}

__device__ __forceinline__ void mma_tf32(float* d, const unsigned* a, const unsigned* b) {
    asm volatile("mma.sync.aligned.m16n8k8.row.col.f32.tf32.tf32.f32 "
                 "{%0,%1,%2,%3}, {%4,%5,%6,%7}, {%8,%9}, {%0,%1,%2,%3};"
                 : "+f"(d[0]), "+f"(d[1]), "+f"(d[2]), "+f"(d[3])
                 : "r"(a[0]), "r"(a[1]), "r"(a[2]), "r"(a[3]),
                   "r"(b[0]), "r"(b[1]));
}

__global__ void __launch_bounds__(128)
gemm_kernel(const float* __restrict__ W,      /* [4032, 64] */
            const float* __restrict__ x,      /* [N, 32]    */
            const float* __restrict__ bias,   /* [64]       */
            float* __restrict__ out)          /* [N, 64]    */
{
    __shared__ float As[BM * AS_S];
    __shared__ float Bs[BK * BS_S];

    int tid  = threadIdx.x;
    int warp = tid >> 5;
    int lane = tid & 31;
    int m0   = blockIdx.x * BM;

    float acc[8][4];
#pragma unroll
    for (int j = 0; j < 8; ++j)
#pragma unroll
        for (int i = 0; i < 4; ++i) acc[j][i] = 0.f;

    const int NCH = KDIM / BK;   /* 126 chunks */
    for (int ch = 0; ch < NCH; ++ch) {
        int j0 = ch * BK;

        /* ---- load A tile 64x32 (4 float4 per thread) ---- */
#pragma unroll
        for (int i = 0; i < 4; ++i) {
            int q   = tid + 128 * i;
            int row = q >> 3;
            int cv  = q & 7;
            int node = m0 + row;
            int nc   = node < N_NODES ? node : N_NODES - 1;
            float4 v;
            if (j0 < KSPL) {
                v = *(const float4*)(g_T + (size_t)nc * KSPL + j0 + cv * 4);
            } else {
                float dg = fmaxf(g_deg[nc], 1.0f);
                v = *(const float4*)(x + (size_t)nc * FIN + cv * 4);
                v.x *= dg; v.y *= dg; v.z *= dg; v.w *= dg;
            }
            float* a = As + row * AS_S + cv * 4;
            a[0] = to_tf32(v.x); a[1] = to_tf32(v.y);
            a[2] = to_tf32(v.z); a[3] = to_tf32(v.w);
        }

        /* ---- load B tile 32x64 ---- */
#pragma unroll
        for (int i = 0; i < 4; ++i) {
            int q   = tid + 128 * i;
            int row = q >> 4;
            int cv  = q & 15;
            float4 v = *(const float4*)(W + (size_t)(j0 + row) * FOUT + cv * 4);
            float* b = Bs + row * BS_S + cv * 4;
            b[0] = to_tf32(v.x); b[1] = to_tf32(v.y);
            b[2] = to_tf32(v.z); b[3] = to_tf32(v.w);
        }
        __syncthreads();

        /* ---- compute ---- */
#pragma unroll
        for (int kk = 0; kk < BK; kk += 8) {
            unsigned a[4];
            int ar = warp * 16 + (lane >> 2);
            int ac = kk + (lane & 3);
            a[0] = __float_as_uint(As[ar * AS_S + ac]);
            a[1] = __float_as_uint(As[(ar + 8) * AS_S + ac]);
            a[2] = __float_as_uint(As[ar * AS_S + ac + 4]);
            a[3] = __float_as_uint(As[(ar + 8) * AS_S + ac + 4]);
#pragma unroll
            for (int j = 0; j < 8; ++j) {
                unsigned b[2];
                int bk = kk + (lane & 3);
                int bn = j * 8 + (lane >> 2);
                b[0] = __float_as_uint(Bs[bk * BS_S + bn]);
                b[1] = __float_as_uint(Bs[(bk + 4) * BS_S + bn]);
                mma_tf32(acc[j], a, b);
            }
        }
        __syncthreads();
    }

    /* ---- epilogue: /deg + bias ---- */
    int r  = lane >> 2;
    int cp = (lane & 3) * 2;
    int n0 = m0 + warp * 16 + r;
#pragma unroll
    for (int j = 0; j < 8; ++j) {
        int col = j * 8 + cp;
        if (n0 < N_NODES) {
            float dg = fmaxf(g_deg[n0], 1.0f);
            out[(size_t)n0 * FOUT + col]     = acc[j][0] / dg + bias[col];
            out[(size_t)n0 * FOUT + col + 1] = acc[j][1] / dg + bias[col + 1];
        }
        if (n0 + 8 < N_NODES) {
            float dg = fmaxf(g_deg[n0 + 8], 1.0f);
            out[(size_t)(n0 + 8) * FOUT + col]     = acc[j][2] / dg + bias[col];
            out[(size_t)(n0 + 8) * FOUT + col + 1] = acc[j][3] / dg + bias[col + 1];
        }
    }
}

/* ------------------------------------------------------------------ */
extern "C" void kernel_launch(void* const* d_in, const int* in_sizes, int n_in,
                              void* d_out, int out_size)
{
    const float* x      = (const float*)d_in[0];
    const int*   ei     = (const int*)d_in[1];       /* int32 edge_index */
    const float* pseudo = (const float*)d_in[2];
    const float* weight = (const float*)d_in[3];     /* [126,32,64] == [4032,64] */
    const float* bias   = (const float*)d_in[4];
    float*       out    = (float*)d_out;

    long E = (long)in_sizes[1] / 2;

    float4* Tptr;   cudaGetSymbolAddress((void**)&Tptr, g_T);
    float4* Dptr;   cudaGetSymbolAddress((void**)&Dptr, g_deg);

    /* zero T (800MB) and deg */
    {
        long n4 = (long)N_NODES * KSPL / 4;
        int blocks = (int)((n4 + 255) / 256);
        zero_f4<<<blocks, 256>>>(Tptr, n4);
        long d4 = N_NODES / 4;
        zero_f4<<<(int)((d4 + 255) / 256), 256>>>(Dptr, d4);
    }

    /* scatter */
    {
        long threads = E * 8;
        int blocks = (int)((threads + 255) / 256);
        scatter_kernel<<<blocks, 256>>>(x, ei, pseudo, E);
    }

    /* GEMM + epilogue */
    {
        int blocks = (N_NODES + BM - 1) / BM;   /* 782 */
        gemm_kernel<<<blocks, 128>>>(weight, x, bias, out);
    }
}

// round 5
// speedup vs baseline: 1.7183x; 1.7183x over previous
#include <cuda_runtime.h>
#include <cuda_fp16.h>
#include <cstdint>

#define N_NODES 50000
#define FIN     32
#define FOUT    64
#define KPTS    125
#define KSPL    (KPTS * FIN)      /* 4000 : spline K-dim     */
#define NCHUNK  126               /* 126 K-chunks of 32      */

/* 400 MB fp16 scratch for the scattered (node, kpoint, f_in) tensor */
__device__ __half g_T[(size_t)N_NODES * KSPL];
__device__ float  g_deg[N_NODES];
/* fragment-ordered fp16 weights: [126 chunks][2 ksteps][8 ntiles][32 lanes] x uint2 */
__device__ uint2  g_Wfrag[NCHUNK * 2 * 8 * 32];

/* ------------------------------------------------------------------ */
/* Pre-pass: repack W[4032,64] fp32 into mma-fragment-ordered fp16.   */
__global__ void wfrag_kernel(const float* __restrict__ W) {
    int t = blockIdx.x * blockDim.x + threadIdx.x;
    if (t >= NCHUNK * 2 * 8 * 32) return;
    int lane = t & 31;
    int j    = (t >> 5) & 7;
    int ks   = (t >> 8) & 1;
    int ch   = t >> 9;
    int n  = j * 8 + (lane >> 2);
    int k0 = ch * 32 + ks * 16 + (lane & 3) * 2;
    __half2 r0 = __floats2half2_rn(W[(size_t)k0 * 64 + n],
                                   W[(size_t)(k0 + 1) * 64 + n]);
    __half2 r1 = __floats2half2_rn(W[(size_t)(k0 + 8) * 64 + n],
                                   W[(size_t)(k0 + 9) * 64 + n]);
    g_Wfrag[t] = make_uint2(*(unsigned*)&r0, *(unsigned*)&r1);
}

/* ------------------------------------------------------------------ */
/* Scatter: 4 lanes per edge, each lane owns 8 features (v4.f16x2).   */
__global__ void __launch_bounds__(256)
scatter_kernel(const float* __restrict__ x,
               const int* __restrict__ ei,
               const float* __restrict__ pseudo,
               long E)
{
    long t    = (long)blockIdx.x * blockDim.x + threadIdx.x;
    int  lane = (int)(t & 3);
    long e    = t >> 2;
    if (e >= E) return;

    int dst = ei[e];
    int src = ei[E + e];

    float p0 = pseudo[e * 3 + 0] * 4.0f;
    float p1 = pseudo[e * 3 + 1] * 4.0f;
    float p2 = pseudo[e * 3 + 2] * 4.0f;
    float f0 = floorf(p0), f1 = floorf(p1), f2 = floorf(p2);
    float r0 = p0 - f0,    r1 = p1 - f1,    r2 = p2 - f2;
    int   i0 = (int)f0,    i1 = (int)f1,    i2 = (int)f2;

    const float4 xa = *(const float4*)(x + (size_t)src * FIN + lane * 8);
    const float4 xb = *(const float4*)(x + (size_t)src * FIN + lane * 8 + 4);

    if (lane == 0) atomicAdd(&g_deg[dst], 1.0f);

    __half* Tb = g_T + (size_t)dst * KSPL + lane * 8;

#pragma unroll
    for (int s = 0; s < 8; ++s) {
        int   b0 = s & 1, b1 = (s >> 1) & 1, b2 = (s >> 2) & 1;
        float basis = (b0 ? r0 : 1.0f - r0)
                    * (b1 ? r1 : 1.0f - r1)
                    * (b2 ? r2 : 1.0f - r2);
        int c0 = i0 + b0; if (c0 >= 5) c0 -= 5;
        int c1 = i1 + b1; if (c1 >= 5) c1 -= 5;
        int c2 = i2 + b2; if (c2 >= 5) c2 -= 5;
        int wi = c0 + 5 * c1 + 25 * c2;

        __half2 v0 = __floats2half2_rn(basis * xa.x, basis * xa.y);
        __half2 v1 = __floats2half2_rn(basis * xa.z, basis * xa.w);
        __half2 v2 = __floats2half2_rn(basis * xb.x, basis * xb.y);
        __half2 v3 = __floats2half2_rn(basis * xb.z, basis * xb.w);

        __half* ptr = Tb + (size_t)wi * FIN;
        asm volatile("red.global.add.noftz.v4.f16x2 [%0], {%1,%2,%3,%4};"
                     :: "l"(ptr),
                        "r"(*(unsigned*)&v0), "r"(*(unsigned*)&v1),
                        "r"(*(unsigned*)&v2), "r"(*(unsigned*)&v3)
                     : "memory");
    }
}

/* ------------------------------------------------------------------ */
/* fp16 tensor-core GEMM: out[N,64] = A[N,4032] @ W[4032,64]          */
/* A rows: [ fp16 T[n,0:4000] | fp16(x[n,:]*max(deg,1)) ]             */
/* B comes pre-fragmented from g_Wfrag (no smem, coalesced + L1).     */

#define BM   128
#define AS_S 56     /* fp16 stride: 112B, 16B-aligned, conflict-free frag LDS */

__device__ __forceinline__ void mma_f16(float* d, const unsigned* a, const unsigned* b) {
    asm volatile("mma.sync.aligned.m16n8k16.row.col.f32.f16.f16.f32 "
                 "{%0,%1,%2,%3}, {%4,%5,%6,%7}, {%8,%9}, {%0,%1,%2,%3};"
                 : "+f"(d[0]), "+f"(d[1]), "+f"(d[2]), "+f"(d[3])
                 : "r"(a[0]), "r"(a[1]), "r"(a[2]), "r"(a[3]),
                   "r"(b[0]), "r"(b[1]));
}

__global__ void __launch_bounds__(256)
gemm_kernel(const float* __restrict__ x,
            const float* __restrict__ bias,
            float* __restrict__ out)
{
    __shared__ __half As[BM * AS_S];

    int tid  = threadIdx.x;
    int warp = tid >> 5;           /* 0..7, each owns 16 rows */
    int lane = tid & 31;
    int m0   = blockIdx.x * BM;

    float acc[8][4];
#pragma unroll
    for (int j = 0; j < 8; ++j)
#pragma unroll
        for (int i = 0; i < 4; ++i) acc[j][i] = 0.f;

    for (int ch = 0; ch < NCHUNK; ++ch) {
        /* ---- load A tile: 128 rows x 32 fp16 ---- */
#pragma unroll
        for (int i = 0; i < 2; ++i) {
            int q    = tid + 256 * i;
            int row  = q >> 2;
            int cv   = q & 3;          /* 16B (8 fp16) vector column */
            int node = m0 + row;
            int nc   = node < N_NODES ? node : N_NODES - 1;
            if (ch < KPTS) {
                uint4 v = *(const uint4*)(g_T + (size_t)nc * KSPL + ch * 32 + cv * 8);
                *(uint4*)(As + row * AS_S + cv * 8) = v;
            } else {
                float dg = fmaxf(g_deg[nc], 1.0f);
                float4 a = *(const float4*)(x + (size_t)nc * FIN + cv * 8);
                float4 b = *(const float4*)(x + (size_t)nc * FIN + cv * 8 + 4);
                __half2 p0 = __floats2half2_rn(a.x * dg, a.y * dg);
                __half2 p1 = __floats2half2_rn(a.z * dg, a.w * dg);
                __half2 p2 = __floats2half2_rn(b.x * dg, b.y * dg);
                __half2 p3 = __floats2half2_rn(b.z * dg, b.w * dg);
                *(uint4*)(As + row * AS_S + cv * 8) =
                    make_uint4(*(unsigned*)&p0, *(unsigned*)&p1,
                               *(unsigned*)&p2, *(unsigned*)&p3);
            }
        }
        __syncthreads();

        /* ---- compute: 2 k-steps x 8 n-tiles ---- */
        int ar = warp * 16 + (lane >> 2);
        int ac = (lane & 3) * 2;
#pragma unroll
        for (int ks = 0; ks < 2; ++ks) {
            unsigned a[4];
            int c = ks * 16 + ac;
            a[0] = *(const unsigned*)(As + ar * AS_S + c);
            a[1] = *(const unsigned*)(As + (ar + 8) * AS_S + c);
            a[2] = *(const unsigned*)(As + ar * AS_S + c + 8);
            a[3] = *(const unsigned*)(As + (ar + 8) * AS_S + c + 8);
            const uint2* wf = g_Wfrag + ((size_t)(ch * 2 + ks) * 8) * 32 + lane;
#pragma unroll
            for (int j = 0; j < 8; ++j) {
                uint2 bv = wf[j * 32];
                unsigned b[2] = { bv.x, bv.y };
                mma_f16(acc[j], a, b);
            }
        }
        __syncthreads();
    }

    /* ---- epilogue: /deg + bias ---- */
    int r  = lane >> 2;
    int cp = (lane & 3) * 2;
    int n0 = m0 + warp * 16 + r;
#pragma unroll
    for (int j = 0; j < 8; ++j) {
        int col = j * 8 + cp;
        if (n0 < N_NODES) {
            float dg = fmaxf(g_deg[n0], 1.0f);
            out[(size_t)n0 * FOUT + col]     = acc[j][0] / dg + bias[col];
            out[(size_t)n0 * FOUT + col + 1] = acc[j][1] / dg + bias[col + 1];
        }
        if (n0 + 8 < N_NODES) {
            float dg = fmaxf(g_deg[n0 + 8], 1.0f);
            out[(size_t)(n0 + 8) * FOUT + col]     = acc[j][2] / dg + bias[col];
            out[(size_t)(n0 + 8) * FOUT + col + 1] = acc[j][3] / dg + bias[col + 1];
        }
    }
}

/* ------------------------------------------------------------------ */
extern "C" void kernel_launch(void* const* d_in, const int* in_sizes, int n_in,
                              void* d_out, int out_size)
{
    const float* x      = (const float*)d_in[0];
    const int*   ei     = (const int*)d_in[1];
    const float* pseudo = (const float*)d_in[2];
    const float* weight = (const float*)d_in[3];   /* [126,32,64] */
    const float* bias   = (const float*)d_in[4];
    float*       out    = (float*)d_out;

    long E = (long)in_sizes[1] / 2;

    void *Tptr, *Dptr;
    cudaGetSymbolAddress(&Tptr, g_T);
    cudaGetSymbolAddress(&Dptr, g_deg);

    /* repack weights into fragment order (tiny; launch before big memset) */
    wfrag_kernel<<<(NCHUNK * 2 * 8 * 32 + 255) / 256, 256>>>(weight);

    /* zero T (400MB fp16) and deg via graph-capturable memset nodes */
    cudaMemsetAsync(Tptr, 0, (size_t)N_NODES * KSPL * sizeof(__half), 0);
    cudaMemsetAsync(Dptr, 0, (size_t)N_NODES * sizeof(float), 0);

    /* scatter */
    {
        long threads = E * 4;
        int blocks = (int)((threads + 255) / 256);
        scatter_kernel<<<blocks, 256>>>(x, ei, pseudo, E);
    }

    /* GEMM + epilogue */
    gemm_kernel<<<(N_NODES + BM - 1) / BM, 256>>>(x, bias, out);
}

// round 6
// speedup vs baseline: 1.9488x; 1.1341x over previous
#include <cuda_runtime.h>
#include <cuda_fp16.h>
#include <cstdint>

#define N_NODES 50000
#define FIN     32
#define FOUT    64
#define KPTS    125
#define KROW    4032              /* 126 chunks * 32 : per-node A row   */
#define NCHUNK  126

/* 403 MB fp16 scratch: per node [125 spline chunks | 1 root chunk] x 32 */
__device__ __half g_T[(size_t)N_NODES * KROW];
__device__ float  g_deg[N_NODES];
/* fragment-ordered fp16 weights: [126 chunks][2 ksteps][8 ntiles][32 lanes] x uint2 */
__device__ uint2  g_Wfrag[NCHUNK * 2 * 8 * 32];

/* ------------------------------------------------------------------ */
__global__ void wfrag_kernel(const float* __restrict__ W) {
    int t = blockIdx.x * blockDim.x + threadIdx.x;
    if (t >= NCHUNK * 2 * 8 * 32) return;
    int lane = t & 31;
    int j    = (t >> 5) & 7;
    int ks   = (t >> 8) & 1;
    int ch   = t >> 9;
    int n  = j * 8 + (lane >> 2);
    int k0 = ch * 32 + ks * 16 + (lane & 3) * 2;
    __half2 r0 = __floats2half2_rn(W[(size_t)k0 * 64 + n],
                                   W[(size_t)(k0 + 1) * 64 + n]);
    __half2 r1 = __floats2half2_rn(W[(size_t)(k0 + 8) * 64 + n],
                                   W[(size_t)(k0 + 9) * 64 + n]);
    g_Wfrag[t] = make_uint2(*(unsigned*)&r0, *(unsigned*)&r1);
}

/* ------------------------------------------------------------------ */
/* Scatter: 4 lanes per edge, each lane owns 8 features (v4.f16x2).   */
__global__ void __launch_bounds__(256)
scatter_kernel(const float* __restrict__ x,
               const int* __restrict__ ei,
               const float* __restrict__ pseudo,
               long E)
{
    long t    = (long)blockIdx.x * blockDim.x + threadIdx.x;
    int  lane = (int)(t & 3);
    long e    = t >> 2;
    if (e >= E) return;

    int dst = ei[e];
    int src = ei[E + e];

    float p0 = pseudo[e * 3 + 0] * 4.0f;
    float p1 = pseudo[e * 3 + 1] * 4.0f;
    float p2 = pseudo[e * 3 + 2] * 4.0f;
    float f0 = floorf(p0), f1 = floorf(p1), f2 = floorf(p2);
    float r0 = p0 - f0,    r1 = p1 - f1,    r2 = p2 - f2;
    int   i0 = (int)f0,    i1 = (int)f1,    i2 = (int)f2;

    const float4 xa = *(const float4*)(x + (size_t)src * FIN + lane * 8);
    const float4 xb = *(const float4*)(x + (size_t)src * FIN + lane * 8 + 4);

    if (lane == 0) atomicAdd(&g_deg[dst], 1.0f);

    __half* Tb = g_T + (size_t)dst * KROW + lane * 8;

#pragma unroll
    for (int s = 0; s < 8; ++s) {
        int   b0 = s & 1, b1 = (s >> 1) & 1, b2 = (s >> 2) & 1;
        float basis = (b0 ? r0 : 1.0f - r0)
                    * (b1 ? r1 : 1.0f - r1)
                    * (b2 ? r2 : 1.0f - r2);
        int c0 = i0 + b0; if (c0 >= 5) c0 -= 5;
        int c1 = i1 + b1; if (c1 >= 5) c1 -= 5;
        int c2 = i2 + b2; if (c2 >= 5) c2 -= 5;
        int wi = c0 + 5 * c1 + 25 * c2;

        __half2 v0 = __floats2half2_rn(basis * xa.x, basis * xa.y);
        __half2 v1 = __floats2half2_rn(basis * xa.z, basis * xa.w);
        __half2 v2 = __floats2half2_rn(basis * xb.x, basis * xb.y);
        __half2 v3 = __floats2half2_rn(basis * xb.z, basis * xb.w);

        __half* ptr = Tb + (size_t)wi * FIN;
        asm volatile("red.global.add.noftz.v4.f16x2 [%0], {%1,%2,%3,%4};"
                     :: "l"(ptr),
                        "r"(*(unsigned*)&v0), "r"(*(unsigned*)&v1),
                        "r"(*(unsigned*)&v2), "r"(*(unsigned*)&v3)
                     : "memory");
    }
}

/* ------------------------------------------------------------------ */
/* Root-chunk fill: g_T[n, 4000:4032] = fp16(x[n,:] * max(deg,1))     */
__global__ void rootfill_kernel(const float* __restrict__ x) {
    int t = blockIdx.x * blockDim.x + threadIdx.x;
    if (t >= N_NODES * 4) return;
    int n = t >> 2, cv = t & 3;
    float dg = fmaxf(g_deg[n], 1.0f);
    float4 a = *(const float4*)(x + (size_t)n * FIN + cv * 8);
    float4 b = *(const float4*)(x + (size_t)n * FIN + cv * 8 + 4);
    __half2 p0 = __floats2half2_rn(a.x * dg, a.y * dg);
    __half2 p1 = __floats2half2_rn(a.z * dg, a.w * dg);
    __half2 p2 = __floats2half2_rn(b.x * dg, b.y * dg);
    __half2 p3 = __floats2half2_rn(b.z * dg, b.w * dg);
    *(uint4*)(g_T + (size_t)n * KROW + KPTS * FIN + cv * 8) =
        make_uint4(*(unsigned*)&p0, *(unsigned*)&p1,
                   *(unsigned*)&p2, *(unsigned*)&p3);
}

/* ------------------------------------------------------------------ */
/* fp16 tensor-core GEMM with 3-stage cp.async pipeline on A tiles.   */

#define BM    128
#define AS_S  56      /* fp16 stride: 112B, 16B aligned               */
#define STG   3
#define ATILE (BM * AS_S)

__device__ __forceinline__ void cp_async16(__half* smem_dst, const __half* gsrc) {
    unsigned s = (unsigned)__cvta_generic_to_shared(smem_dst);
    asm volatile("cp.async.cg.shared.global [%0], [%1], 16;" :: "r"(s), "l"(gsrc));
}

__device__ __forceinline__ void mma_f16(float* d, const unsigned* a, const unsigned* b) {
    asm volatile("mma.sync.aligned.m16n8k16.row.col.f32.f16.f16.f32 "
                 "{%0,%1,%2,%3}, {%4,%5,%6,%7}, {%8,%9}, {%0,%1,%2,%3};"
                 : "+f"(d[0]), "+f"(d[1]), "+f"(d[2]), "+f"(d[3])
                 : "r"(a[0]), "r"(a[1]), "r"(a[2]), "r"(a[3]),
                   "r"(b[0]), "r"(b[1]));
}

__global__ void __launch_bounds__(256)
gemm_kernel(const float* __restrict__ bias, float* __restrict__ out)
{
    __shared__ __half As[STG * ATILE];

    int tid  = threadIdx.x;
    int warp = tid >> 5;
    int lane = tid & 31;
    int m0   = blockIdx.x * BM;

    /* per-thread A-load coordinates (2 x 16B per chunk) */
    int lrow0 = tid >> 2;          /* 0..63   */
    int lrow1 = lrow0 + 64;        /* 64..127 */
    int lcv   = tid & 3;
    int nc0 = m0 + lrow0; if (nc0 >= N_NODES) nc0 = N_NODES - 1;
    int nc1 = m0 + lrow1; if (nc1 >= N_NODES) nc1 = N_NODES - 1;
    const __half* src0 = g_T + (size_t)nc0 * KROW + lcv * 8;
    const __half* src1 = g_T + (size_t)nc1 * KROW + lcv * 8;
    __half* dst0 = As + lrow0 * AS_S + lcv * 8;
    __half* dst1 = As + lrow1 * AS_S + lcv * 8;

    float acc[8][4];
#pragma unroll
    for (int j = 0; j < 8; ++j)
#pragma unroll
        for (int i = 0; i < 4; ++i) acc[j][i] = 0.f;

    /* prologue: stages 0 and 1 in flight */
#pragma unroll
    for (int p = 0; p < 2; ++p) {
        cp_async16(dst0 + p * ATILE, src0 + p * 32);
        cp_async16(dst1 + p * ATILE, src1 + p * 32);
        asm volatile("cp.async.commit_group;");
    }

    int ar = warp * 16 + (lane >> 2);
    int ac = (lane & 3) * 2;

    for (int ch = 0; ch < NCHUNK; ++ch) {
        int stage = ch % STG;
        asm volatile("cp.async.wait_group 1;");
        __syncthreads();

        const __half* A = As + stage * ATILE;
#pragma unroll
        for (int ks = 0; ks < 2; ++ks) {
            unsigned a[4];
            int c = ks * 16 + ac;
            a[0] = *(const unsigned*)(A + ar * AS_S + c);
            a[1] = *(const unsigned*)(A + (ar + 8) * AS_S + c);
            a[2] = *(const unsigned*)(A + ar * AS_S + c + 8);
            a[3] = *(const unsigned*)(A + (ar + 8) * AS_S + c + 8);
            const uint2* wf = g_Wfrag + ((size_t)(ch * 2 + ks) * 8) * 32 + lane;
#pragma unroll
            for (int j = 0; j < 8; ++j) {
                uint2 bv = wf[j * 32];
                unsigned b[2] = { bv.x, bv.y };
                mma_f16(acc[j], a, b);
            }
        }
        __syncthreads();

        int nx = ch + 2;
        if (nx < NCHUNK) {
            int ns = nx % STG;
            cp_async16(dst0 + ns * ATILE, src0 + nx * 32);
            cp_async16(dst1 + ns * ATILE, src1 + nx * 32);
        }
        asm volatile("cp.async.commit_group;");
    }

    /* ---- epilogue: /deg + bias ---- */
    int r  = lane >> 2;
    int cp = (lane & 3) * 2;
    int n0 = m0 + warp * 16 + r;
#pragma unroll
    for (int j = 0; j < 8; ++j) {
        int col = j * 8 + cp;
        if (n0 < N_NODES) {
            float dg = fmaxf(g_deg[n0], 1.0f);
            out[(size_t)n0 * FOUT + col]     = acc[j][0] / dg + bias[col];
            out[(size_t)n0 * FOUT + col + 1] = acc[j][1] / dg + bias[col + 1];
        }
        if (n0 + 8 < N_NODES) {
            float dg = fmaxf(g_deg[n0 + 8], 1.0f);
            out[(size_t)(n0 + 8) * FOUT + col]     = acc[j][2] / dg + bias[col];
            out[(size_t)(n0 + 8) * FOUT + col + 1] = acc[j][3] / dg + bias[col + 1];
        }
    }
}

/* ------------------------------------------------------------------ */
extern "C" void kernel_launch(void* const* d_in, const int* in_sizes, int n_in,
                              void* d_out, int out_size)
{
    const float* x      = (const float*)d_in[0];
    const int*   ei     = (const int*)d_in[1];
    const float* pseudo = (const float*)d_in[2];
    const float* weight = (const float*)d_in[3];   /* [126,32,64] */
    const float* bias   = (const float*)d_in[4];
    float*       out    = (float*)d_out;

    long E = (long)in_sizes[1] / 2;

    void *Tptr, *Dptr;
    cudaGetSymbolAddress(&Tptr, g_T);
    cudaGetSymbolAddress(&Dptr, g_deg);

    /* repack weights into fragment order (tiny) */
    wfrag_kernel<<<(NCHUNK * 2 * 8 * 32 + 255) / 256, 256>>>(weight);

    /* zero T (403MB fp16) and deg */
    cudaMemsetAsync(Tptr, 0, (size_t)N_NODES * KROW * sizeof(__half), 0);
    cudaMemsetAsync(Dptr, 0, (size_t)N_NODES * sizeof(float), 0);

    /* scatter */
    {
        long threads = E * 4;
        int blocks = (int)((threads + 255) / 256);
        scatter_kernel<<<blocks, 256>>>(x, ei, pseudo, E);
    }

    /* root chunk: x * deg */
    rootfill_kernel<<<(N_NODES * 4 + 255) / 256, 256>>>(x);

    /* GEMM + epilogue */
    gemm_kernel<<<(N_NODES + BM - 1) / BM, 256>>>(bias, out);
}

// round 7
// speedup vs baseline: 2.0158x; 1.0344x over previous
#include <cuda_runtime.h>
#include <cuda_fp16.h>
#include <cstdint>

#define N_NODES 50000
#define FIN     32
#define FOUT    64
#define KPTS    125
#define KROW    4032              /* 126 chunks * 32 : per-node A row   */
#define NCHUNK  126
#define NDCH    63                /* double-chunks of 64 columns        */

/* 403 MB fp16 scratch: per node [125 spline chunks | 1 root chunk] x 32 */
__device__ __half g_T[(size_t)N_NODES * KROW];
__device__ float  g_deg[N_NODES];
/* fragment-ordered fp16 weights: [252 ksteps][8 ntiles][32 lanes] x uint2 */
__device__ uint2  g_Wfrag[NCHUNK * 2 * 8 * 32];

/* ------------------------------------------------------------------ */
__global__ void wfrag_kernel(const float* __restrict__ W) {
    int t = blockIdx.x * blockDim.x + threadIdx.x;
    if (t >= NCHUNK * 2 * 8 * 32) return;
    int lane = t & 31;
    int j    = (t >> 5) & 7;
    int ks   = (t >> 8) & 1;
    int ch   = t >> 9;
    int n  = j * 8 + (lane >> 2);
    int k0 = ch * 32 + ks * 16 + (lane & 3) * 2;
    __half2 r0 = __floats2half2_rn(W[(size_t)k0 * 64 + n],
                                   W[(size_t)(k0 + 1) * 64 + n]);
    __half2 r1 = __floats2half2_rn(W[(size_t)(k0 + 8) * 64 + n],
                                   W[(size_t)(k0 + 9) * 64 + n]);
    g_Wfrag[t] = make_uint2(*(unsigned*)&r0, *(unsigned*)&r1);
}

/* ------------------------------------------------------------------ */
/* Scatter: 4 lanes per edge, each lane owns 8 features (v4.f16x2).   */
__global__ void __launch_bounds__(256)
scatter_kernel(const float* __restrict__ x,
               const int* __restrict__ ei,
               const float* __restrict__ pseudo,
               long E)
{
    long t    = (long)blockIdx.x * blockDim.x + threadIdx.x;
    int  lane = (int)(t & 3);
    long e    = t >> 2;
    if (e >= E) return;

    int dst = ei[e];
    int src = ei[E + e];

    float p0 = pseudo[e * 3 + 0] * 4.0f;
    float p1 = pseudo[e * 3 + 1] * 4.0f;
    float p2 = pseudo[e * 3 + 2] * 4.0f;
    float f0 = floorf(p0), f1 = floorf(p1), f2 = floorf(p2);
    float r0 = p0 - f0,    r1 = p1 - f1,    r2 = p2 - f2;
    int   i0 = (int)f0,    i1 = (int)f1,    i2 = (int)f2;

    const float4 xa = *(const float4*)(x + (size_t)src * FIN + lane * 8);
    const float4 xb = *(const float4*)(x + (size_t)src * FIN + lane * 8 + 4);

    if (lane == 0) atomicAdd(&g_deg[dst], 1.0f);

    __half* Tb = g_T + (size_t)dst * KROW + lane * 8;

#pragma unroll
    for (int s = 0; s < 8; ++s) {
        int   b0 = s & 1, b1 = (s >> 1) & 1, b2 = (s >> 2) & 1;
        float basis = (b0 ? r0 : 1.0f - r0)
                    * (b1 ? r1 : 1.0f - r1)
                    * (b2 ? r2 : 1.0f - r2);
        int c0 = i0 + b0; if (c0 >= 5) c0 -= 5;
        int c1 = i1 + b1; if (c1 >= 5) c1 -= 5;
        int c2 = i2 + b2; if (c2 >= 5) c2 -= 5;
        int wi = c0 + 5 * c1 + 25 * c2;

        __half2 v0 = __floats2half2_rn(basis * xa.x, basis * xa.y);
        __half2 v1 = __floats2half2_rn(basis * xa.z, basis * xa.w);
        __half2 v2 = __floats2half2_rn(basis * xb.x, basis * xb.y);
        __half2 v3 = __floats2half2_rn(basis * xb.z, basis * xb.w);

        __half* ptr = Tb + (size_t)wi * FIN;
        asm volatile("red.global.add.noftz.v4.f16x2 [%0], {%1,%2,%3,%4};"
                     :: "l"(ptr),
                        "r"(*(unsigned*)&v0), "r"(*(unsigned*)&v1),
                        "r"(*(unsigned*)&v2), "r"(*(unsigned*)&v3)
                     : "memory");
    }
}

/* ------------------------------------------------------------------ */
/* Root-chunk fill: g_T[n, 4000:4032] = fp16(x[n,:] * max(deg,1))     */
__global__ void rootfill_kernel(const float* __restrict__ x) {
    int t = blockIdx.x * blockDim.x + threadIdx.x;
    if (t >= N_NODES * 4) return;
    int n = t >> 2, cv = t & 3;
    float dg = fmaxf(g_deg[n], 1.0f);
    float4 a = *(const float4*)(x + (size_t)n * FIN + cv * 8);
    float4 b = *(const float4*)(x + (size_t)n * FIN + cv * 8 + 4);
    __half2 p0 = __floats2half2_rn(a.x * dg, a.y * dg);
    __half2 p1 = __floats2half2_rn(a.z * dg, a.w * dg);
    __half2 p2 = __floats2half2_rn(b.x * dg, b.y * dg);
    __half2 p3 = __floats2half2_rn(b.z * dg, b.w * dg);
    *(uint4*)(g_T + (size_t)n * KROW + KPTS * FIN + cv * 8) =
        make_uint4(*(unsigned*)&p0, *(unsigned*)&p1,
                   *(unsigned*)&p2, *(unsigned*)&p3);
}

/* ------------------------------------------------------------------ */
/* fp16 tensor-core GEMM, double-chunk (64-col) 2-stage cp.async ring */

#define BM     128
#define DS     72                 /* padded stage row stride (fp16)   */
#define ATILE2 (BM * DS)          /* 9216 fp16 = 18KB per stage       */

__device__ __forceinline__ void cp_async16(__half* smem_dst, const __half* gsrc) {
    unsigned s = (unsigned)__cvta_generic_to_shared(smem_dst);
    asm volatile("cp.async.cg.shared.global [%0], [%1], 16;" :: "r"(s), "l"(gsrc));
}

__device__ __forceinline__ void mma_f16(float* d, const unsigned* a, const unsigned* b) {
    asm volatile("mma.sync.aligned.m16n8k16.row.col.f32.f16.f16.f32 "
                 "{%0,%1,%2,%3}, {%4,%5,%6,%7}, {%8,%9}, {%0,%1,%2,%3};"
                 : "+f"(d[0]), "+f"(d[1]), "+f"(d[2]), "+f"(d[3])
                 : "r"(a[0]), "r"(a[1]), "r"(a[2]), "r"(a[3]),
                   "r"(b[0]), "r"(b[1]));
}

__global__ void __launch_bounds__(256, 4)
gemm_kernel(const float* __restrict__ bias, float* __restrict__ out)
{
    __shared__ __half As[2 * ATILE2];   /* 36 KB */

    int tid  = threadIdx.x;
    int warp = tid >> 5;
    int lane = tid & 31;
    int m0   = blockIdx.x * BM;

    /* A-load coords: thread t owns 64 contiguous bytes of one row */
    int lrow = tid >> 1;           /* 0..127 */
    int half = tid & 1;            /* which 32-fp16 half of the 64-col stage */
    int nc = m0 + lrow; if (nc >= N_NODES) nc = N_NODES - 1;
    const __half* srcA = g_T + (size_t)nc * KROW + half * 32;
    __half*       dstA = As + lrow * DS + half * 32;

    float acc[8][4];
#pragma unroll
    for (int j = 0; j < 8; ++j)
#pragma unroll
        for (int i = 0; i < 4; ++i) acc[j][i] = 0.f;

    /* prologue: stage 0 */
#pragma unroll
    for (int i = 0; i < 4; ++i)
        cp_async16(dstA + i * 8, srcA + i * 8);
    asm volatile("cp.async.commit_group;");

    int ar = warp * 16 + (lane >> 2);
    int ac = (lane & 3) * 2;

    for (int d = 0; d < NDCH; ++d) {
        /* issue next stage */
        if (d + 1 < NDCH) {
            __half*       dn = dstA + ((d + 1) & 1) * ATILE2;
            const __half* sn = srcA + (size_t)(d + 1) * 64;
#pragma unroll
            for (int i = 0; i < 4; ++i)
                cp_async16(dn + i * 8, sn + i * 8);
        }
        asm volatile("cp.async.commit_group;");
        asm volatile("cp.async.wait_group 1;");
        __syncthreads();

        const __half* A = As + (d & 1) * ATILE2;
        const uint2*  wfd = g_Wfrag + (size_t)(4 * d) * 256 + lane;
#pragma unroll
        for (int ks = 0; ks < 4; ++ks) {
            unsigned a[4];
            int c = ks * 16 + ac;
            a[0] = *(const unsigned*)(A + ar * DS + c);
            a[1] = *(const unsigned*)(A + (ar + 8) * DS + c);
            a[2] = *(const unsigned*)(A + ar * DS + c + 8);
            a[3] = *(const unsigned*)(A + (ar + 8) * DS + c + 8);
            const uint2* wf = wfd + (size_t)ks * 256;
#pragma unroll
            for (int j = 0; j < 8; ++j) {
                uint2 bv = wf[j * 32];
                unsigned b[2] = { bv.x, bv.y };
                mma_f16(acc[j], a, b);
            }
        }
        __syncthreads();
    }

    /* ---- epilogue: /deg + bias ---- */
    int r  = lane >> 2;
    int cp = (lane & 3) * 2;
    int n0 = m0 + warp * 16 + r;
#pragma unroll
    for (int j = 0; j < 8; ++j) {
        int col = j * 8 + cp;
        if (n0 < N_NODES) {
            float dg = fmaxf(g_deg[n0], 1.0f);
            out[(size_t)n0 * FOUT + col]     = acc[j][0] / dg + bias[col];
            out[(size_t)n0 * FOUT + col + 1] = acc[j][1] / dg + bias[col + 1];
        }
        if (n0 + 8 < N_NODES) {
            float dg = fmaxf(g_deg[n0 + 8], 1.0f);
            out[(size_t)(n0 + 8) * FOUT + col]     = acc[j][2] / dg + bias[col];
            out[(size_t)(n0 + 8) * FOUT + col + 1] = acc[j][3] / dg + bias[col + 1];
        }
    }
}

/* ------------------------------------------------------------------ */
extern "C" void kernel_launch(void* const* d_in, const int* in_sizes, int n_in,
                              void* d_out, int out_size)
{
    const float* x      = (const float*)d_in[0];
    const int*   ei     = (const int*)d_in[1];
    const float* pseudo = (const float*)d_in[2];
    const float* weight = (const float*)d_in[3];   /* [126,32,64] */
    const float* bias   = (const float*)d_in[4];
    float*       out    = (float*)d_out;

    long E = (long)in_sizes[1] / 2;

    void *Tptr, *Dptr;
    cudaGetSymbolAddress(&Tptr, g_T);
    cudaGetSymbolAddress(&Dptr, g_deg);

    /* repack weights into fragment order (tiny) */
    wfrag_kernel<<<(NCHUNK * 2 * 8 * 32 + 255) / 256, 256>>>(weight);

    /* zero T (403MB fp16) and deg */
    cudaMemsetAsync(Tptr, 0, (size_t)N_NODES * KROW * sizeof(__half), 0);
    cudaMemsetAsync(Dptr, 0, (size_t)N_NODES * sizeof(float), 0);

    /* scatter */
    {
        long threads = E * 4;
        int blocks = (int)((threads + 255) / 256);
        scatter_kernel<<<blocks, 256>>>(x, ei, pseudo, E);
    }

    /* root chunk: x * deg */
    rootfill_kernel<<<(N_NODES * 4 + 255) / 256, 256>>>(x);

    /* GEMM + epilogue */
    gemm_kernel<<<(N_NODES + BM - 1) / BM, 256>>>(bias, out);
}

// round 8
// speedup vs baseline: 2.0328x; 1.0084x over previous
#include <cuda_runtime.h>
#include <cuda_fp16.h>
#include <cstdint>

#define N_NODES 50000
#define FIN     32
#define FOUT    64
#define KPTS    125
#define KROW    4032              /* 126 chunks * 32 : per-node A row   */
#define NCHUNK  126
#define NDCH    63                /* double-chunks of 64 columns        */
#define KSPLIT  4
#define DPG     16                /* double-chunks per K-group (last: 15) */

/* 403 MB fp16 scratch: per node [125 spline chunks | 1 root chunk] x 32 */
__device__ __half g_T[(size_t)N_NODES * KROW];
__device__ float  g_deg[N_NODES];
/* fragment-ordered fp16 weights: [252 ksteps][8 ntiles][32 lanes] x uint2 */
__device__ uint2  g_Wfrag[NCHUNK * 2 * 8 * 32];
/* split-K partial outputs: [KSPLIT][N][64] fp32 (51 MB) */
__device__ float  g_part[(size_t)KSPLIT * N_NODES * FOUT];

/* ------------------------------------------------------------------ */
__global__ void wfrag_kernel(const float* __restrict__ W) {
    int t = blockIdx.x * blockDim.x + threadIdx.x;
    if (t >= NCHUNK * 2 * 8 * 32) return;
    int lane = t & 31;
    int j    = (t >> 5) & 7;
    int ks   = (t >> 8) & 1;
    int ch   = t >> 9;
    int n  = j * 8 + (lane >> 2);
    int k0 = ch * 32 + ks * 16 + (lane & 3) * 2;
    __half2 r0 = __floats2half2_rn(W[(size_t)k0 * 64 + n],
                                   W[(size_t)(k0 + 1) * 64 + n]);
    __half2 r1 = __floats2half2_rn(W[(size_t)(k0 + 8) * 64 + n],
                                   W[(size_t)(k0 + 9) * 64 + n]);
    g_Wfrag[t] = make_uint2(*(unsigned*)&r0, *(unsigned*)&r1);
}

/* ------------------------------------------------------------------ */
/* Scatter: 4 lanes per edge, each lane owns 8 features (v4.f16x2).   */
__global__ void __launch_bounds__(256)
scatter_kernel(const float* __restrict__ x,
               const int* __restrict__ ei,
               const float* __restrict__ pseudo,
               long E)
{
    long t    = (long)blockIdx.x * blockDim.x + threadIdx.x;
    int  lane = (int)(t & 3);
    long e    = t >> 2;
    if (e >= E) return;

    int dst = ei[e];
    int src = ei[E + e];

    float p0 = pseudo[e * 3 + 0] * 4.0f;
    float p1 = pseudo[e * 3 + 1] * 4.0f;
    float p2 = pseudo[e * 3 + 2] * 4.0f;
    float f0 = floorf(p0), f1 = floorf(p1), f2 = floorf(p2);
    float r0 = p0 - f0,    r1 = p1 - f1,    r2 = p2 - f2;
    int   i0 = (int)f0,    i1 = (int)f1,    i2 = (int)f2;

    const float4 xa = *(const float4*)(x + (size_t)src * FIN + lane * 8);
    const float4 xb = *(const float4*)(x + (size_t)src * FIN + lane * 8 + 4);

    if (lane == 0) atomicAdd(&g_deg[dst], 1.0f);

    __half* Tb = g_T + (size_t)dst * KROW + lane * 8;

#pragma unroll
    for (int s = 0; s < 8; ++s) {
        int   b0 = s & 1, b1 = (s >> 1) & 1, b2 = (s >> 2) & 1;
        float basis = (b0 ? r0 : 1.0f - r0)
                    * (b1 ? r1 : 1.0f - r1)
                    * (b2 ? r2 : 1.0f - r2);
        int c0 = i0 + b0; if (c0 >= 5) c0 -= 5;
        int c1 = i1 + b1; if (c1 >= 5) c1 -= 5;
        int c2 = i2 + b2; if (c2 >= 5) c2 -= 5;
        int wi = c0 + 5 * c1 + 25 * c2;

        __half2 v0 = __floats2half2_rn(basis * xa.x, basis * xa.y);
        __half2 v1 = __floats2half2_rn(basis * xa.z, basis * xa.w);
        __half2 v2 = __floats2half2_rn(basis * xb.x, basis * xb.y);
        __half2 v3 = __floats2half2_rn(basis * xb.z, basis * xb.w);

        __half* ptr = Tb + (size_t)wi * FIN;
        asm volatile("red.global.add.noftz.v4.f16x2 [%0], {%1,%2,%3,%4};"
                     :: "l"(ptr),
                        "r"(*(unsigned*)&v0), "r"(*(unsigned*)&v1),
                        "r"(*(unsigned*)&v2), "r"(*(unsigned*)&v3)
                     : "memory");
    }
}

/* ------------------------------------------------------------------ */
/* Root-chunk fill: g_T[n, 4000:4032] = fp16(x[n,:] * max(deg,1))     */
__global__ void rootfill_kernel(const float* __restrict__ x) {
    int t = blockIdx.x * blockDim.x + threadIdx.x;
    if (t >= N_NODES * 4) return;
    int n = t >> 2, cv = t & 3;
    float dg = fmaxf(g_deg[n], 1.0f);
    float4 a = *(const float4*)(x + (size_t)n * FIN + cv * 8);
    float4 b = *(const float4*)(x + (size_t)n * FIN + cv * 8 + 4);
    __half2 p0 = __floats2half2_rn(a.x * dg, a.y * dg);
    __half2 p1 = __floats2half2_rn(a.z * dg, a.w * dg);
    __half2 p2 = __floats2half2_rn(b.x * dg, b.y * dg);
    __half2 p3 = __floats2half2_rn(b.z * dg, b.w * dg);
    *(uint4*)(g_T + (size_t)n * KROW + KPTS * FIN + cv * 8) =
        make_uint4(*(unsigned*)&p0, *(unsigned*)&p1,
                   *(unsigned*)&p2, *(unsigned*)&p3);
}

/* ------------------------------------------------------------------ */
/* fp16 tensor-core GEMM, split-K x4, 64-col double-chunk 2-stage ring */

#define BM     128
#define DS     72                 /* padded stage row stride (fp16)   */
#define ATILE2 (BM * DS)          /* 18KB per stage                   */

__device__ __forceinline__ void cp_async16(__half* smem_dst, const __half* gsrc) {
    unsigned s = (unsigned)__cvta_generic_to_shared(smem_dst);
    asm volatile("cp.async.cg.shared.global [%0], [%1], 16;" :: "r"(s), "l"(gsrc));
}

__device__ __forceinline__ void mma_f16(float* d, const unsigned* a, const unsigned* b) {
    asm volatile("mma.sync.aligned.m16n8k16.row.col.f32.f16.f16.f32 "
                 "{%0,%1,%2,%3}, {%4,%5,%6,%7}, {%8,%9}, {%0,%1,%2,%3};"
                 : "+f"(d[0]), "+f"(d[1]), "+f"(d[2]), "+f"(d[3])
                 : "r"(a[0]), "r"(a[1]), "r"(a[2]), "r"(a[3]),
                   "r"(b[0]), "r"(b[1]));
}

__global__ void __launch_bounds__(256, 4)
gemm_kernel(void)
{
    __shared__ __half As[2 * ATILE2];   /* 36 KB */

    int tid  = threadIdx.x;
    int warp = tid >> 5;
    int lane = tid & 31;
    int m0   = blockIdx.x * BM;
    int grp  = blockIdx.y;
    int d0   = grp * DPG;
    int d1   = d0 + DPG; if (d1 > NDCH) d1 = NDCH;

    /* A-load coords: thread t owns 64 contiguous bytes of one row */
    int lrow = tid >> 1;
    int half = tid & 1;
    int nc = m0 + lrow; if (nc >= N_NODES) nc = N_NODES - 1;
    const __half* srcA = g_T + (size_t)nc * KROW + half * 32;
    __half*       dstA = As + lrow * DS + half * 32;

    float acc[8][4];
#pragma unroll
    for (int j = 0; j < 8; ++j)
#pragma unroll
        for (int i = 0; i < 4; ++i) acc[j][i] = 0.f;

    /* prologue: first stage of this group */
#pragma unroll
    for (int i = 0; i < 4; ++i)
        cp_async16(dstA + (d0 & 1) * ATILE2 + i * 8, srcA + (size_t)d0 * 64 + i * 8);
    asm volatile("cp.async.commit_group;");

    int ar = warp * 16 + (lane >> 2);
    int ac = (lane & 3) * 2;

    for (int d = d0; d < d1; ++d) {
        if (d + 1 < d1) {
            __half*       dn = dstA + ((d + 1) & 1) * ATILE2;
            const __half* sn = srcA + (size_t)(d + 1) * 64;
#pragma unroll
            for (int i = 0; i < 4; ++i)
                cp_async16(dn + i * 8, sn + i * 8);
        }
        asm volatile("cp.async.commit_group;");
        asm volatile("cp.async.wait_group 1;");
        __syncthreads();

        const __half* A = As + (d & 1) * ATILE2;
        const uint2*  wfd = g_Wfrag + (size_t)(4 * d) * 256 + lane;
#pragma unroll
        for (int ks = 0; ks < 4; ++ks) {
            unsigned a[4];
            int c = ks * 16 + ac;
            a[0] = *(const unsigned*)(A + ar * DS + c);
            a[1] = *(const unsigned*)(A + (ar + 8) * DS + c);
            a[2] = *(const unsigned*)(A + ar * DS + c + 8);
            a[3] = *(const unsigned*)(A + (ar + 8) * DS + c + 8);
            const uint2* wf = wfd + (size_t)ks * 256;
#pragma unroll
            for (int j = 0; j < 8; ++j) {
                uint2 bv = wf[j * 32];
                unsigned b[2] = { bv.x, bv.y };
                mma_f16(acc[j], a, b);
            }
        }
        __syncthreads();
    }

    /* ---- epilogue: /deg, store partial (coalesced, no atomics) ---- */
    float* part = g_part + (size_t)grp * N_NODES * FOUT;
    int r  = lane >> 2;
    int cp = (lane & 3) * 2;
    int n0 = m0 + warp * 16 + r;
#pragma unroll
    for (int j = 0; j < 8; ++j) {
        int col = j * 8 + cp;
        if (n0 < N_NODES) {
            float dg = fmaxf(g_deg[n0], 1.0f);
            part[(size_t)n0 * FOUT + col]     = acc[j][0] / dg;
            part[(size_t)n0 * FOUT + col + 1] = acc[j][1] / dg;
        }
        if (n0 + 8 < N_NODES) {
            float dg = fmaxf(g_deg[n0 + 8], 1.0f);
            part[(size_t)(n0 + 8) * FOUT + col]     = acc[j][2] / dg;
            part[(size_t)(n0 + 8) * FOUT + col + 1] = acc[j][3] / dg;
        }
    }
}

/* ------------------------------------------------------------------ */
/* Reduce: out = sum of 4 partials + bias                             */
__global__ void reduce_kernel(const float* __restrict__ bias,
                              float* __restrict__ out)
{
    int t = blockIdx.x * blockDim.x + threadIdx.x;   /* float4 index */
    if (t >= N_NODES * FOUT / 4) return;
    const size_t stride = (size_t)N_NODES * FOUT / 4;
    const float4* p = (const float4*)g_part;
    float4 a = p[t];
    float4 b = p[t + stride];
    float4 c = p[t + 2 * stride];
    float4 d = p[t + 3 * stride];
    int col = (t & 15) * 4;
    float4 o;
    o.x = a.x + b.x + c.x + d.x + bias[col];
    o.y = a.y + b.y + c.y + d.y + bias[col + 1];
    o.z = a.z + b.z + c.z + d.z + bias[col + 2];
    o.w = a.w + b.w + c.w + d.w + bias[col + 3];
    ((float4*)out)[t] = o;
}

/* ------------------------------------------------------------------ */
extern "C" void kernel_launch(void* const* d_in, const int* in_sizes, int n_in,
                              void* d_out, int out_size)
{
    const float* x      = (const float*)d_in[0];
    const int*   ei     = (const int*)d_in[1];
    const float* pseudo = (const float*)d_in[2];
    const float* weight = (const float*)d_in[3];   /* [126,32,64] */
    const float* bias   = (const float*)d_in[4];
    float*       out    = (float*)d_out;

    long E = (long)in_sizes[1] / 2;

    void *Tptr, *Dptr;
    cudaGetSymbolAddress(&Tptr, g_T);
    cudaGetSymbolAddress(&Dptr, g_deg);

    /* repack weights into fragment order (tiny) */
    wfrag_kernel<<<(NCHUNK * 2 * 8 * 32 + 255) / 256, 256>>>(weight);

    /* zero T (403MB fp16) and deg */
    cudaMemsetAsync(Tptr, 0, (size_t)N_NODES * KROW * sizeof(__half), 0);
    cudaMemsetAsync(Dptr, 0, (size_t)N_NODES * sizeof(float), 0);

    /* scatter */
    {
        long threads = E * 4;
        int blocks = (int)((threads + 255) / 256);
        scatter_kernel<<<blocks, 256>>>(x, ei, pseudo, E);
    }

    /* root chunk: x * deg */
    rootfill_kernel<<<(N_NODES * 4 + 255) / 256, 256>>>(x);

    /* split-K GEMM -> partials, then reduce(+bias) */
    {
        dim3 grid((N_NODES + BM - 1) / BM, KSPLIT);
        gemm_kernel<<<grid, 256>>>();
        reduce_kernel<<<(N_NODES * FOUT / 4 + 255) / 256, 256>>>(bias, out);
    }
}